// round 7
// baseline (speedup 1.0000x reference)
#include <cuda_runtime.h>
#include <math.h>

// Problem constants (fixed by the dataset reference)
constexpr int B   = 4;
constexpr int N   = 10;
constexpr int K   = 5;
constexpr int Q   = 512;
constexpr int D   = 1536;         // 2 * HID
constexpr int T1  = D / 4;        // 384 float4 lanes per row
constexpr int QC  = 128;          // query chunks per batch (4 rows each)
constexpr int QPC = Q / QC;       // 4 rows per chunk
constexpr int SEGS = 32;          // K2 segments per batch
constexpr int LPS  = T1 / SEGS;   // 12 lanes per K2 segment (= warps/block)
constexpr int CPT  = QC / 32;     // 4 chunks per thread in K2

// Scratch (allocation-free: __device__ globals) — lives in L2 between kernels
__device__ float4 g_psum[QC * B * T1];   // per-chunk column sums   (3 MB)
__device__ float  g_psumsq[QC * B * T1]; // per-chunk per-lane sumsq
__device__ float4 g_xbar[B * T1];        // final column mean (already / Q)
__device__ float  g_cpart[B * T1];       // per-lane total sumsq (pre / Q)

// ---------------------------------------------------------------------------
// K1: query partial reduction.
// grid=(B,QC)=512 blocks, 384 threads, 4 rows/thread, loads batched up front.
// ~3.4 blocks/SM -> ~40 warps/SM -> ~5 MB of LDG in flight chip-wide.
// ---------------------------------------------------------------------------
__global__ __launch_bounds__(T1) void qreduce_kernel(const float* __restrict__ query)
{
    const int t  = threadIdx.x;
    const int b  = blockIdx.x;
    const int qc = blockIdx.y;

    const float4* qp = reinterpret_cast<const float4*>(query)
                     + (size_t)b * Q * T1 + (size_t)qc * QPC * T1 + t;

    // Batch all 4 independent loads before any consumption.
    float4 v[QPC];
    #pragma unroll
    for (int i = 0; i < QPC; ++i) v[i] = qp[(size_t)i * T1];

    float4 s  = make_float4(0.f, 0.f, 0.f, 0.f);
    float  s2 = 0.f;
    #pragma unroll
    for (int i = 0; i < QPC; ++i) {
        s.x += v[i].x; s.y += v[i].y; s.z += v[i].z; s.w += v[i].w;
        s2  += v[i].x * v[i].x + v[i].y * v[i].y
             + v[i].z * v[i].z + v[i].w * v[i].w;
    }
    const int idx = (qc * B + b) * T1 + t;
    g_psum[idx]   = s;
    g_psumsq[idx] = s2;
}

// ---------------------------------------------------------------------------
// K2: collapse QC=128 partial chunks into x_bar + per-lane sumsq totals.
// grid=(B,SEGS)=128 blocks, 384 threads.  Warp w <-> lane seg*12+w.
// Thread (w,lid) reduces chunks {lid, lid+32, lid+64, lid+96}; all L2 hits.
// ---------------------------------------------------------------------------
__global__ __launch_bounds__(T1) void collapse_kernel()
{
    const int t   = threadIdx.x;
    const int b   = blockIdx.x;
    const int seg = blockIdx.y;
    const int w   = t >> 5;        // 0..11 -> lane offset within segment
    const int lid = t & 31;

    const int lane = seg * LPS + w;

    float4 v  = make_float4(0.f, 0.f, 0.f, 0.f);
    float  s2 = 0.f;
    #pragma unroll
    for (int j = 0; j < CPT; ++j) {
        const int qc  = lid + 32 * j;
        const int idx = (qc * B + b) * T1 + lane;
        float4 p = g_psum[idx];
        v.x += p.x; v.y += p.y; v.z += p.z; v.w += p.w;
        s2  += g_psumsq[idx];
    }

    #pragma unroll
    for (int off = 16; off > 0; off >>= 1) {
        v.x += __shfl_xor_sync(0xFFFFFFFFu, v.x, off);
        v.y += __shfl_xor_sync(0xFFFFFFFFu, v.y, off);
        v.z += __shfl_xor_sync(0xFFFFFFFFu, v.z, off);
        v.w += __shfl_xor_sync(0xFFFFFFFFu, v.w, off);
        s2  += __shfl_xor_sync(0xFFFFFFFFu, s2, off);
    }
    if (lid == 0) {
        constexpr float invQ = 1.0f / (float)Q;
        g_xbar[b * T1 + lane]  = make_float4(v.x * invQ, v.y * invQ,
                                             v.z * invQ, v.w * invQ);
        g_cpart[b * T1 + lane] = s2;
    }
}

// ---------------------------------------------------------------------------
// K3: per-(b,n) prototype block.  grid=40, 384 threads.
// All global loads issued up front (5x support + xbar + cpart -> MLP 7).
// ---------------------------------------------------------------------------
__global__ __launch_bounds__(T1) void proto_kernel(const float* __restrict__ support,
                                                   float* __restrict__ out)
{
    const int t = threadIdx.x;
    const int b = blockIdx.x / N;
    const int n = blockIdx.x % N;

    constexpr float invQ = 1.0f / (float)Q;
    constexpr int   NV   = 2 * K + 2;   // 5 dots, 5 norms, cpart, pad

    const float4* sp = reinterpret_cast<const float4*>(support)
                     + ((size_t)(b * N + n) * K) * T1 + t;

    float4 s4[K];
    #pragma unroll
    for (int k = 0; k < K; ++k) s4[k] = sp[(size_t)k * T1];
    const float4 xb = g_xbar[b * T1 + t];
    const float  cp = g_cpart[b * T1 + t];

    float vals[NV];
    #pragma unroll
    for (int k = 0; k < K; ++k) {
        float4 v = s4[k];
        vals[k]     = v.x * xb.x + v.y * xb.y + v.z * xb.z + v.w * xb.w;
        vals[K + k] = v.x * v.x + v.y * v.y + v.z * v.z + v.w * v.w;
    }
    vals[2 * K]     = cp;
    vals[2 * K + 1] = 0.f;

    constexpr int NW = T1 / 32;
    __shared__ float red[NW][NV];
    __shared__ float wsh[K];
    const int wid = t >> 5, lid = t & 31;
    #pragma unroll
    for (int j = 0; j < NV; ++j) {
        float v = vals[j];
        #pragma unroll
        for (int off = 16; off > 0; off >>= 1)
            v += __shfl_xor_sync(0xFFFFFFFFu, v, off);
        if (lid == 0) red[wid][j] = v;
    }
    __syncthreads();

    if (t == 0) {
        float tot[NV];
        #pragma unroll
        for (int j = 0; j < 2 * K + 1; ++j) {
            float a = 0.f;
            #pragma unroll
            for (int w2 = 0; w2 < NW; ++w2) a += red[w2][j];
            tot[j] = a;
        }
        const float c = tot[2 * K] * invQ;     // mean_q ||x_q||^2
        float tk[K], mx = -1e30f;
        #pragma unroll
        for (int k = 0; k < K; ++k) {
            // mean_q -||s - x_q||^2 = -(||s||^2 - 2 s.xbar + c)
            const float m = -(tot[K + k] - 2.0f * tot[k] + c);
            tk[k] = tanhf(m);
            mx = fmaxf(mx, tk[k]);
        }
        float sum = 0.f, e[K];
        #pragma unroll
        for (int k = 0; k < K; ++k) { e[k] = expf(tk[k] - mx); sum += e[k]; }
        const float inv = 1.0f / sum;
        #pragma unroll
        for (int k = 0; k < K; ++k) {
            const float w = e[k] * inv;
            wsh[k] = w;
            out[(size_t)B * N * D + (size_t)(b * N + n) * K + k] = w;  // qgw
        }
    }
    __syncthreads();

    float4 a = make_float4(0.f, 0.f, 0.f, 0.f);
    #pragma unroll
    for (int k = 0; k < K; ++k) {
        const float w = wsh[k];
        a.x += s4[k].x * w; a.y += s4[k].y * w;
        a.z += s4[k].z * w; a.w += s4[k].w * w;
    }
    reinterpret_cast<float4*>(out)[(size_t)(b * N + n) * T1 + t] = a;
}

extern "C" void kernel_launch(void* const* d_in, const int* in_sizes, int n_in,
                              void* d_out, int out_size)
{
    const float* support = (const float*)d_in[0];  // (B, N, K, D)
    const float* query   = (const float*)d_in[1];  // (B, Q, D)
    float* out = (float*)d_out;                    // agg (B,N,D) then qgw (B,N,K,1)

    dim3 g1(B, QC);
    qreduce_kernel<<<g1, T1>>>(query);
    dim3 g2(B, SEGS);
    collapse_kernel<<<g2, T1>>>();
    proto_kernel<<<B * N, T1>>>(support, out);
}

// round 8
// speedup vs baseline: 1.2113x; 1.2113x over previous
#include <cuda_runtime.h>
#include <math.h>

constexpr int B   = 4;
constexpr int N   = 10;
constexpr int K   = 5;
constexpr int Q   = 512;
constexpr int D   = 1536;          // 2 * HID
constexpr int T1  = D / 4;         // 384 float4 lanes
constexpr int QC  = 32;            // chunks per batch
constexpr int QPC = Q / QC;        // 16 rows per chunk
constexpr int GRID = B * QC;       // 128 blocks (all co-resident)
constexpr int NTHR = 768;
constexpr int HALFQ = QPC / 2;     // 8 rows per thread in phase 1
constexpr int LPS  = T1 / QC;      // 12 lanes per phase-2 segment

// Scratch: transposed partials so phase-2 warp reads are contiguous.
__device__ float4 g_psumT[B * T1 * QC];    // [(b*T1+lane)*QC + qc]
__device__ float  g_psumsqT[B * T1 * QC];
__device__ float4 g_xbar[B * T1];
__device__ float  g_cpart[B * T1];
__device__ unsigned int g_t1, g_t2;        // monotonic barrier tickets

__device__ __forceinline__ void grid_barrier(unsigned int* ctr, int tid, bool spin)
{
    __syncthreads();                 // all block writes done
    if (tid == 0) {
        __threadfence();             // publish before arriving
        unsigned my = atomicAdd(ctr, 1u) + 1u;
        if (spin) {
            unsigned target = ((my + (unsigned)GRID - 1u) / (unsigned)GRID) * (unsigned)GRID;
            for (;;) {
                unsigned v;
                asm volatile("ld.acquire.gpu.u32 %0, [%1];" : "=r"(v) : "l"(ctr));
                if (v >= target) break;
                __nanosleep(32);
            }
        }
    }
    __syncthreads();
}

__global__ __launch_bounds__(NTHR, 1)
void fused_kernel(const float* __restrict__ support,
                  const float* __restrict__ query,
                  float* __restrict__ out)
{
    const int t    = threadIdx.x;
    const int half = t / T1;           // 0 or 1
    const int lane = t - half * T1;    // 0..383

    __shared__ float4 shp[NTHR];
    __shared__ float  shp2[NTHR];

    constexpr float invQ = 1.0f / (float)Q;

    // ===================== Phase 1: query partial reduce =====================
    {
        const int b  = blockIdx.x >> 5;
        const int qc = blockIdx.x & 31;

        const float4* qp = reinterpret_cast<const float4*>(query)
                         + (size_t)(b * Q + qc * QPC + half * HALFQ) * T1 + lane;

        float4 v[HALFQ];                       // batch all 8 loads (MLP=8/thread)
        #pragma unroll
        for (int i = 0; i < HALFQ; ++i) v[i] = qp[(size_t)i * T1];

        float4 s  = make_float4(0.f, 0.f, 0.f, 0.f);
        float  s2 = 0.f;
        #pragma unroll
        for (int i = 0; i < HALFQ; ++i) {
            s.x += v[i].x; s.y += v[i].y; s.z += v[i].z; s.w += v[i].w;
            s2  += v[i].x * v[i].x + v[i].y * v[i].y
                 + v[i].z * v[i].z + v[i].w * v[i].w;
        }
        shp[t] = s; shp2[t] = s2;
        __syncthreads();
        if (half == 0) {
            float4 o = shp[t + T1];
            const int idx = (b * T1 + lane) * QC + qc;   // transposed
            g_psumT[idx]   = make_float4(s.x + o.x, s.y + o.y, s.z + o.z, s.w + o.w);
            g_psumsqT[idx] = s2 + shp2[t + T1];
        }
    }

    grid_barrier(&g_t1, t, true);

    // ============ Phase 2: collapse QC chunks, warp-per-lane ================
    // Block (b, seg): warps 0..11 own lanes seg*12..seg*12+11.
    // Thread = one chunk: contiguous 512B warp reads from L2, shfl reduce.
    if (t < T1) {
        const int b   = blockIdx.x >> 5;
        const int seg = blockIdx.x & 31;
        const int w   = t >> 5;
        const int lid = t & 31;
        if (w < LPS) {
            const int ln  = seg * LPS + w;
            const int idx = (b * T1 + ln) * QC + lid;
            float4 v  = g_psumT[idx];
            float  s2 = g_psumsqT[idx];
            #pragma unroll
            for (int off = 16; off > 0; off >>= 1) {
                v.x += __shfl_xor_sync(0xFFFFFFFFu, v.x, off);
                v.y += __shfl_xor_sync(0xFFFFFFFFu, v.y, off);
                v.z += __shfl_xor_sync(0xFFFFFFFFu, v.z, off);
                v.w += __shfl_xor_sync(0xFFFFFFFFu, v.w, off);
                s2  += __shfl_xor_sync(0xFFFFFFFFu, s2, off);
            }
            if (lid == 0) {
                g_xbar[b * T1 + ln]  = make_float4(v.x * invQ, v.y * invQ,
                                                   v.z * invQ, v.w * invQ);
                g_cpart[b * T1 + ln] = s2;
            }
        }
    }

    const bool is_proto = (blockIdx.x < B * N);
    grid_barrier(&g_t2, t, is_proto);          // non-proto blocks just arrive
    if (!is_proto) return;

    // ===================== Phase 3: per-(b,n) prototype ======================
    if (t >= T1) return;
    const int b = blockIdx.x / N;
    const int n = blockIdx.x % N;
    constexpr int NV = 2 * K + 2;
    constexpr int NW = T1 / 32;

    const float4* sp = reinterpret_cast<const float4*>(support)
                     + ((size_t)(b * N + n) * K) * T1 + t;

    float4 s4[K];
    #pragma unroll
    for (int k = 0; k < K; ++k) s4[k] = sp[(size_t)k * T1];
    const float4 xb = g_xbar[b * T1 + t];
    const float  cp = g_cpart[b * T1 + t];

    float vals[NV];
    #pragma unroll
    for (int k = 0; k < K; ++k) {
        float4 v = s4[k];
        vals[k]     = v.x * xb.x + v.y * xb.y + v.z * xb.z + v.w * xb.w;
        vals[K + k] = v.x * v.x + v.y * v.y + v.z * v.z + v.w * v.w;
    }
    vals[2 * K]     = cp;
    vals[2 * K + 1] = 0.f;

    __shared__ float red[NW][NV];
    __shared__ float wsh[K];
    const int wid = t >> 5, lid = t & 31;
    #pragma unroll
    for (int j = 0; j < NV; ++j) {
        float v = vals[j];
        #pragma unroll
        for (int off = 16; off > 0; off >>= 1)
            v += __shfl_xor_sync(0xFFFFFFFFu, v, off);
        if (lid == 0) red[wid][j] = v;
    }
    __syncthreads();

    if (t == 0) {
        float tot[NV];
        #pragma unroll
        for (int j = 0; j < 2 * K + 1; ++j) {
            float a = 0.f;
            #pragma unroll
            for (int w2 = 0; w2 < NW; ++w2) a += red[w2][j];
            tot[j] = a;
        }
        const float c = tot[2 * K] * invQ;
        float tk[K], mx = -1e30f;
        #pragma unroll
        for (int k = 0; k < K; ++k) {
            const float m = -(tot[K + k] - 2.0f * tot[k] + c);
            tk[k] = tanhf(m);
            mx = fmaxf(mx, tk[k]);
        }
        float sum = 0.f, e[K];
        #pragma unroll
        for (int k = 0; k < K; ++k) { e[k] = expf(tk[k] - mx); sum += e[k]; }
        const float inv = 1.0f / sum;
        #pragma unroll
        for (int k = 0; k < K; ++k) {
            const float w = e[k] * inv;
            wsh[k] = w;
            out[(size_t)B * N * D + (size_t)(b * N + n) * K + k] = w;   // qgw
        }
    }
    __syncthreads();

    float4 a = make_float4(0.f, 0.f, 0.f, 0.f);
    #pragma unroll
    for (int k = 0; k < K; ++k) {
        const float w = wsh[k];
        a.x += s4[k].x * w; a.y += s4[k].y * w;
        a.z += s4[k].z * w; a.w += s4[k].w * w;
    }
    reinterpret_cast<float4*>(out)[(size_t)(b * N + n) * T1 + t] = a;
}

extern "C" void kernel_launch(void* const* d_in, const int* in_sizes, int n_in,
                              void* d_out, int out_size)
{
    const float* support = (const float*)d_in[0];  // (B, N, K, D)
    const float* query   = (const float*)d_in[1];  // (B, Q, D)
    float* out = (float*)d_out;                    // agg (B,N,D) then qgw (B,N,K,1)

    fused_kernel<<<GRID, NTHR>>>(support, query, out);
}